// round 2
// baseline (speedup 1.0000x reference)
#include <cuda_runtime.h>
#include <cuda_bf16.h>

// Problem constants (fixed by the dataset)
#define B_COLS   64            // dense columns
#define N_MAX    50048         // neuron count (50000) rounded up a bit
#define NNZ_MAX  800000

// Scratch (no allocation allowed): ping-pong buffers + CSR row pointer
__device__ float g_bufX[N_MAX * B_COLS];
__device__ float g_bufY[N_MAX * B_COLS];
__device__ int   g_row_ptr[N_MAX + 1];

// ---------------------------------------------------------------------------
// Build CSR row_ptr from the sorted `rows` array. For each edge i, fill
// row_ptr[r] for every row r in (rows[i-1], rows[i]]. Thread for i==nnz-1
// also closes the tail. Deterministic, no atomics.
// ---------------------------------------------------------------------------
__global__ void build_row_ptr_kernel(const int* __restrict__ rows, int nnz, int n,
                                     int* __restrict__ row_ptr) {
    int i = blockIdx.x * blockDim.x + threadIdx.x;
    if (i >= nnz) return;
    int r = rows[i];
    int rprev = (i == 0) ? -1 : rows[i - 1];
    for (int rr = rprev + 1; rr <= r; rr++) row_ptr[rr] = i;
    if (i == nnz - 1) {
        for (int rr = r + 1; rr <= n; rr++) row_ptr[rr] = nnz;
    }
}

// ---------------------------------------------------------------------------
// CSR SpMM: out[r, :] = sum_e vals[e] * x[cols[e], :]  (+ bias[r] if HAS_BIAS)
// One warp per row. Lane l owns dense columns {2l, 2l+1} as a float2.
// vals/cols reads are warp-uniform (single broadcast transaction); the x-row
// gather is one coalesced 256B load per edge per warp. Everything stays in L2
// (working set ~40MB << 126MB).
// ---------------------------------------------------------------------------
template <bool HAS_BIAS>
__global__ void __launch_bounds__(256)
spmm_kernel(const float* __restrict__ vals, const int* __restrict__ cols,
            const int* __restrict__ row_ptr, const float* __restrict__ xin,
            const float* __restrict__ bias, float* __restrict__ out, int n) {
    int warp = (blockIdx.x * blockDim.x + threadIdx.x) >> 5;
    int lane = threadIdx.x & 31;
    if (warp >= n) return;

    int s = row_ptr[warp];
    int e = row_ptr[warp + 1];

    const float2* __restrict__ x2 = reinterpret_cast<const float2*>(xin);
    float accx = 0.0f, accy = 0.0f;

    int k = s;
    // Unrolled-by-4 body: 4 independent gathers in flight to cover L2 latency.
    for (; k + 4 <= e; k += 4) {
        float v0 = vals[k + 0]; int c0 = cols[k + 0];
        float v1 = vals[k + 1]; int c1 = cols[k + 1];
        float v2 = vals[k + 2]; int c2 = cols[k + 2];
        float v3 = vals[k + 3]; int c3 = cols[k + 3];
        float2 a0 = x2[c0 * 32 + lane];
        float2 a1 = x2[c1 * 32 + lane];
        float2 a2 = x2[c2 * 32 + lane];
        float2 a3 = x2[c3 * 32 + lane];
        accx += v0 * a0.x; accy += v0 * a0.y;
        accx += v1 * a1.x; accy += v1 * a1.y;
        accx += v2 * a2.x; accy += v2 * a2.y;
        accx += v3 * a3.x; accy += v3 * a3.y;
    }
    for (; k < e; k++) {
        float v = vals[k];
        int   c = cols[k];
        float2 a = x2[c * 32 + lane];
        accx += v * a.x; accy += v * a.y;
    }

    if (HAS_BIAS) {
        float b = bias[warp];
        accx += b; accy += b;
    }
    float2 r; r.x = accx; r.y = accy;
    reinterpret_cast<float2*>(out)[warp * 32 + lane] = r;
}

extern "C" void kernel_launch(void* const* d_in, const int* in_sizes, int n_in,
                              void* d_out, int out_size) {
    const float* x        = (const float*)d_in[0];   // [N, 64]
    const float* adj_vals = (const float*)d_in[1];   // [NNZ]
    const float* w_vals   = (const float*)d_in[2];   // [NNZ]
    const float* bias     = (const float*)d_in[3];   // [N]
    const int*   rows     = (const int*)d_in[4];     // [NNZ] sorted
    const int*   cols     = (const int*)d_in[5];     // [NNZ]
    // n_layers (d_in[6]) lives on device; the problem fixes it at 3.

    const int N   = in_sizes[0] / B_COLS;
    const int NNZ = in_sizes[1];

    float* bufX = nullptr; float* bufY = nullptr; int* row_ptr = nullptr;
    cudaGetSymbolAddress((void**)&bufX, g_bufX);
    cudaGetSymbolAddress((void**)&bufY, g_bufY);
    cudaGetSymbolAddress((void**)&row_ptr, g_row_ptr);

    float* outp = (float*)d_out;

    // 1) row_ptr
    {
        int threads = 256;
        int blocks = (NNZ + threads - 1) / threads;
        build_row_ptr_kernel<<<blocks, threads>>>(rows, NNZ, N, row_ptr);
    }

    // 2) three layers, two SpMMs each; last write goes to d_out
    int threads = 256;
    int warps_per_block = threads / 32;
    int blocks = (N + warps_per_block - 1) / warps_per_block;

    // layer 1
    spmm_kernel<false><<<blocks, threads>>>(w_vals,   cols, row_ptr, x,    nullptr, bufY, N);
    spmm_kernel<true ><<<blocks, threads>>>(adj_vals, cols, row_ptr, bufY, bias,    bufX, N);
    // layer 2
    spmm_kernel<false><<<blocks, threads>>>(w_vals,   cols, row_ptr, bufX, nullptr, bufY, N);
    spmm_kernel<true ><<<blocks, threads>>>(adj_vals, cols, row_ptr, bufY, bias,    bufX, N);
    // layer 3
    spmm_kernel<false><<<blocks, threads>>>(w_vals,   cols, row_ptr, bufX, nullptr, bufY, N);
    spmm_kernel<true ><<<blocks, threads>>>(adj_vals, cols, row_ptr, bufY, bias,    outp, N);
}